// round 15
// baseline (speedup 1.0000x reference)
#include <cuda_runtime.h>
#include <cuda_fp16.h>
#include <cstdint>
#include <cfloat>

// ---------------------------------------------------------------------------
// Problem dims (fixed)
// ---------------------------------------------------------------------------
#define C_DIM   3072
#define HIDDEN  3072
#define KV_DIM  6144
#define N_HEADS 48
#define D_HEAD  64
#define BT      4
#define AA      128
#define HW      1024
#define ROWS_X  (BT * AA)    // 512
#define ROWS_L  (BT * HW)    // 4096

// ---------------------------------------------------------------------------
// Scratch (device globals: allocation-free rule)
// ---------------------------------------------------------------------------
__device__ __half g_xnh[ROWS_X * C_DIM];
__device__ __half g_lnh[ROWS_L * C_DIM];
__device__ __half g_qh [ROWS_L * HIDDEN];
__device__ __half g_kvh[ROWS_X * KV_DIM];
__device__ __half g_aoh[ROWS_L * HIDDEN];
__device__ __half g_wqh [C_DIM * HIDDEN];   // Wq  half [K=3072][N=3072] (orig layout)
__device__ __half g_wkvh[C_DIM * KV_DIM];   // Wkv half [K=3072][N=6144]
__device__ __half g_woh [HIDDEN * C_DIM];   // Wo  half [K=3072][N=3072]

// ---------------------------------------------------------------------------
// Helpers (sm_100-safe: mma.sync fp16 + ldmatrix + cp.async only)
// ---------------------------------------------------------------------------
__device__ __forceinline__ void mma_f16(float* c, const uint32_t* a, const uint32_t* b) {
    asm volatile(
        "mma.sync.aligned.m16n8k16.row.col.f32.f16.f16.f32 "
        "{%0,%1,%2,%3}, {%4,%5,%6,%7}, {%8,%9}, {%0,%1,%2,%3};\n"
        : "+f"(c[0]), "+f"(c[1]), "+f"(c[2]), "+f"(c[3])
        : "r"(a[0]), "r"(a[1]), "r"(a[2]), "r"(a[3]), "r"(b[0]), "r"(b[1]));
}

__device__ __forceinline__ void ldsm_x4(uint32_t* r, uint32_t addr) {
    asm volatile(
        "ldmatrix.sync.aligned.m8n8.x4.shared.b16 {%0,%1,%2,%3}, [%4];\n"
        : "=r"(r[0]), "=r"(r[1]), "=r"(r[2]), "=r"(r[3]) : "r"(addr));
}

__device__ __forceinline__ void ldsm_x4_t(uint32_t* r, uint32_t addr) {
    asm volatile(
        "ldmatrix.sync.aligned.m8n8.x4.trans.shared.b16 {%0,%1,%2,%3}, [%4];\n"
        : "=r"(r[0]), "=r"(r[1]), "=r"(r[2]), "=r"(r[3]) : "r"(addr));
}

__device__ __forceinline__ uint32_t smem_u32(const void* p) {
    uint32_t a;
    asm("{ .reg .u64 t; cvta.to.shared.u64 t, %1; cvt.u32.u64 %0, t; }" : "=r"(a) : "l"(p));
    return a;
}

__device__ __forceinline__ void cpa16(uint32_t dst, const void* src) {
    asm volatile("cp.async.cg.shared.global [%0], [%1], 16;\n" :: "r"(dst), "l"(src) : "memory");
}
#define CP_COMMIT() asm volatile("cp.async.commit_group;\n" ::: "memory")
#define CP_WAIT1()  asm volatile("cp.async.wait_group 1;\n" ::: "memory")

__device__ __forceinline__ uint32_t pack_h2(float a, float b) {
    __half2 h = __floats2half2_rn(a, b);
    return *(uint32_t*)&h;
}

// ---------------------------------------------------------------------------
// Fused prep: weight fp32->fp16 converts + both LayerNorms, one launch.
// ---------------------------------------------------------------------------
#define CVT_WQ_BLKS  ((C_DIM * HIDDEN) / 2048)            // 4608
#define CVT_WKV_BLKS ((C_DIM * KV_DIM) / 2048)            // 9216
#define CVT_WO_BLKS  ((HIDDEN * C_DIM) / 2048)            // 4608
#define CVT_TOTAL    (CVT_WQ_BLKS + CVT_WKV_BLKS + CVT_WO_BLKS)   // 18432
#define PREP_BLKS    (CVT_TOTAL + ROWS_X + ROWS_L)                // 23040

__global__ __launch_bounds__(256)
void prep_kernel(const float* __restrict__ Wq,  __half* __restrict__ wqh,
                 const float* __restrict__ Wkv, __half* __restrict__ wkvh,
                 const float* __restrict__ Wo,  __half* __restrict__ woh,
                 const float* __restrict__ x, const float* __restrict__ latents,
                 const float* __restrict__ g1, const float* __restrict__ b1,
                 const float* __restrict__ g2, const float* __restrict__ b2,
                 __half* __restrict__ xn, __half* __restrict__ lnout)
{
    const int tid = threadIdx.x;
    if (blockIdx.x < CVT_TOTAL) {
        int bx = blockIdx.x;
        const float* in;
        __half* out;
        if (bx < CVT_WQ_BLKS)                      { in = Wq;  out = wqh; }
        else if (bx < CVT_WQ_BLKS + CVT_WKV_BLKS)  { bx -= CVT_WQ_BLKS;  in = Wkv; out = wkvh; }
        else                                       { bx -= CVT_WQ_BLKS + CVT_WKV_BLKS; in = Wo; out = woh; }
        const size_t i = ((size_t)bx * 256 + tid) * 8;
        float4 v0 = *(const float4*)(in + i);
        float4 v1 = *(const float4*)(in + i + 4);
        uint4 o;
        o.x = pack_h2(v0.x, v0.y); o.y = pack_h2(v0.z, v0.w);
        o.z = pack_h2(v1.x, v1.y); o.w = pack_h2(v1.z, v1.w);
        *(uint4*)(out + i) = o;
        return;
    }

    const int row = blockIdx.x - CVT_TOTAL;
    const bool isx = row < ROWS_X;
    const float* xr = isx ? x + (size_t)row * C_DIM
                          : latents + (size_t)(row - ROWS_X) * C_DIM;
    const float* gamma = isx ? g1 : g2;
    const float* beta  = isx ? b1 : b2;
    __half* yr = isx ? xn + (size_t)row * C_DIM
                     : lnout + (size_t)(row - ROWS_X) * C_DIM;

    float4 v[3];
    float s = 0.f, s2 = 0.f;
#pragma unroll
    for (int j = 0; j < 3; j++) {
        v[j] = *(const float4*)(xr + (size_t)(tid + 256 * j) * 4);
        s  += v[j].x + v[j].y + v[j].z + v[j].w;
        s2 += v[j].x*v[j].x + v[j].y*v[j].y + v[j].z*v[j].z + v[j].w*v[j].w;
    }
#pragma unroll
    for (int o = 16; o > 0; o >>= 1) {
        s  += __shfl_xor_sync(0xffffffffu, s, o);
        s2 += __shfl_xor_sync(0xffffffffu, s2, o);
    }
    __shared__ float red[2][8];
    const int w = tid >> 5, lane = tid & 31;
    if (lane == 0) { red[0][w] = s; red[1][w] = s2; }
    __syncthreads();
    float ts = 0.f, ts2 = 0.f;
#pragma unroll
    for (int i = 0; i < 8; i++) { ts += red[0][i]; ts2 += red[1][i]; }
    const float mean = ts * (1.0f / C_DIM);
    const float var  = ts2 * (1.0f / C_DIM) - mean * mean;
    const float rstd = rsqrtf(var + 1e-5f);

#pragma unroll
    for (int j = 0; j < 3; j++) {
        const int c4 = (tid + 256 * j) * 4;
        float4 g = *(const float4*)(gamma + c4);
        float4 b = *(const float4*)(beta  + c4);
        uint2 o;
        o.x = pack_h2((v[j].x - mean) * rstd * g.x + b.x,
                      (v[j].y - mean) * rstd * g.y + b.y);
        o.y = pack_h2((v[j].z - mean) * rstd * g.z + b.z,
                      (v[j].w - mean) * rstd * g.w + b.w);
        *(uint2*)(yr + c4) = o;
    }
}

// ---------------------------------------------------------------------------
// FP16 GEMM v6: warp tile 64x64 (halved LDSM per HMMA — LSU was co-saturated
// with the tensor pipe at 64x32). CTA = 128 threads (4 warps, 2m x 2n),
// block tile 128x128, BKT=64, 3-stage cp.async, 2 CTAs/SM (smem-capped).
// C[M,N] = A[M,K] half (row-major) * B[K,N] half (row-major). N%128, K%64 == 0.
// ---------------------------------------------------------------------------
#define BKT 64
#define A_STRH 72
#define B_STRH 136
#define ASTG_B (128 * A_STRH * 2)        // 18432 B
#define BSTG_B (64 * B_STRH * 2)         // 17408 B
#define G2_SMEM (3 * (ASTG_B + BSTG_B))  // 107520 B
#define GTHREADS 128

template <typename OutT>
__device__ __forceinline__ void gemm_tile(const __half* __restrict__ A,
                                          const __half* __restrict__ B,
                                          OutT* __restrict__ C,
                                          int m0, int n0, int N, int K)
{
    extern __shared__ __half smh[];
    const uint32_t sbase = smem_u32(smh);

    const int tid  = threadIdx.x;
    const int lane = tid & 31;
    const int w    = tid >> 5;        // 0..3
    const int wm   = w >> 1;          // 0..1
    const int wn   = w & 1;           // 0..1
    const int g    = lane >> 2;
    const int tg   = lane & 3;

    const int nk = K / BKT;

    // A ldmatrix lane addr (proven layout), warp m-base wm*64
    const uint32_t a_row = (uint32_t)(wm * 64) + ((lane >> 3) & 1) * 8 + (lane & 7);
    const uint32_t a_col = (uint32_t)(lane >> 4) * 8;
    // B ldmatrix.trans lane addr (proven), warp n-base wn*64
    const uint32_t b_krow = (uint32_t)(((lane >> 3) & 1) * 8 + (lane & 7));
    const uint32_t b_noff = (uint32_t)(lane >> 4) * 8;

    auto fill = [&](int s, int kc) {
        const uint32_t aoff = sbase + (uint32_t)s * ASTG_B;
        const uint32_t boff = sbase + 3 * ASTG_B + (uint32_t)s * BSTG_B;
#pragma unroll
        for (int j = 0; j < 8; j++) {   // A: 128 rows x 8 chunks = 1024 -> 8/thread
            const int f = tid + GTHREADS * j;
            const int row = f >> 3, ch = f & 7;
            cpa16(aoff + row * (A_STRH * 2) + ch * 16,
                  A + (size_t)(m0 + row) * K + kc + ch * 8);
        }
#pragma unroll
        for (int j = 0; j < 8; j++) {   // B: 64 rows x 16 chunks = 1024 -> 8/thread
            const int f = tid + GTHREADS * j;
            const int row = f >> 4, ch = f & 15;
            cpa16(boff + row * (B_STRH * 2) + ch * 16,
                  B + (size_t)(kc + row) * N + n0 + ch * 8);
        }
        CP_COMMIT();
    };

    float acc[4][8][4];
#pragma unroll
    for (int mi = 0; mi < 4; mi++)
#pragma unroll
        for (int ni = 0; ni < 8; ni++)
#pragma unroll
            for (int r = 0; r < 4; r++) acc[mi][ni][r] = 0.f;

    fill(0, 0);
    fill(1, BKT);

    for (int kt = 0; kt < nk; ++kt) {
        CP_WAIT1();
        __syncthreads();

        const int s = kt % 3;
        const uint32_t aBase = sbase + (uint32_t)s * ASTG_B + (a_row * A_STRH + a_col) * 2;
        const uint32_t bBase = sbase + 3 * ASTG_B + (uint32_t)s * BSTG_B
                             + (b_krow * B_STRH + (uint32_t)(wn * 64) + b_noff) * 2;

        // one k-step: 4 B ldsm_t (64 n-cols) + 4 A ldsm (64 m-rows), 32 MMA
        auto kstep = [&](int k0) {
            uint32_t a[4][4], bf[16];
#pragma unroll
            for (int p = 0; p < 4; p++)
                ldsm_x4_t(bf + 4 * p, bBase + (k0 * B_STRH + p * 16) * 2);
#pragma unroll
            for (int mi = 0; mi < 4; mi++)
                ldsm_x4(a[mi], aBase + (mi * 16 * A_STRH + k0) * 2);
#pragma unroll
            for (int mi = 0; mi < 4; mi++)
#pragma unroll
                for (int ni = 0; ni < 8; ni++)
                    mma_f16(acc[mi][ni], a[mi], bf + ni * 2);
        };

        kstep(0);   // LSU serves k-step-0 LDSMs without cp.async contention

        if (kt + 2 < nk) fill((kt + 2) % 3, (kt + 2) * BKT);
        else             CP_COMMIT();   // empty group keeps wait counts aligned

        kstep(16);
        kstep(32);
        kstep(48);
    }

#pragma unroll
    for (int mi = 0; mi < 4; mi++) {
        const int r = m0 + wm * 64 + mi * 16 + g;
#pragma unroll
        for (int ni = 0; ni < 8; ni++) {
            const int c = n0 + wn * 64 + ni * 8 + 2 * tg;
            if constexpr (sizeof(OutT) == 4) {
                *(float2*)&C[(size_t)r * N + c]       = make_float2(acc[mi][ni][0], acc[mi][ni][1]);
                *(float2*)&C[(size_t)(r + 8) * N + c] = make_float2(acc[mi][ni][2], acc[mi][ni][3]);
            } else {
                *(uint32_t*)&C[(size_t)r * N + c]       = pack_h2(acc[mi][ni][0], acc[mi][ni][1]);
                *(uint32_t*)&C[(size_t)(r + 8) * N + c] = pack_h2(acc[mi][ni][2], acc[mi][ni][3]);
            }
        }
    }
}

// Fused Wq + Wkv launch: 1D grid, CTAs [0,768) -> q GEMM, [768,960) -> kv GEMM.
#define QK_SPLIT 768
__global__ __launch_bounds__(GTHREADS, 2)
void gemm_qkv(const __half* __restrict__ ln, const __half* __restrict__ wq,
              __half* __restrict__ q,
              const __half* __restrict__ xn, const __half* __restrict__ wkv,
              __half* __restrict__ kv)
{
    const int bx = blockIdx.x;
    if (bx < QK_SPLIT) {
        gemm_tile<__half>(ln, wq, q, (bx & 31) * 128, (bx >> 5) * 128, HIDDEN, C_DIM);
    } else {
        const int t = bx - QK_SPLIT;
        gemm_tile<__half>(xn, wkv, kv, (t & 3) * 128, (t >> 2) * 128, KV_DIM, C_DIM);
    }
}

// Plain single GEMM (Wo)
template <typename OutT>
__global__ __launch_bounds__(GTHREADS, 2)
void gemm_one(const __half* __restrict__ A, const __half* __restrict__ B,
              OutT* __restrict__ C, int N, int K)
{
    gemm_tile<OutT>(A, B, C, blockIdx.x * 128, blockIdx.y * 128, N, K);
}

// ---------------------------------------------------------------------------
// Attention v3 (R13-proven): tensor-core QK^T + PV, register softmax.
// V staged as-is ([key][d]); PV B-frags via ldmatrix.trans.
// ---------------------------------------------------------------------------
#define AQ_STR 72
#define ATTN2_SMEM (3 * 128 * AQ_STR * 2)   // 55296 B

__global__ __launch_bounds__(256, 2)
void attn2_kernel(const __half* __restrict__ qh, const __half* __restrict__ kvh,
                  __half* __restrict__ ao)
{
    extern __shared__ __half sm2[];
    const uint32_t sq = smem_u32(sm2);
    const uint32_t sk = sq + 128 * AQ_STR * 2;
    const uint32_t sv = sk + 128 * AQ_STR * 2;

    const int tid  = threadIdx.x;
    const int lane = tid & 31;
    const int w    = tid >> 5;
    const int g    = lane >> 2;
    const int tg   = lane & 3;
    const int cq   = blockIdx.x;
    const int h    = blockIdx.y;
    const int bt   = blockIdx.z;
    const int qr0  = cq * 128;

    const __half* qb = qh  + ((size_t)bt * HW + qr0) * HIDDEN + h * D_HEAD;
    const __half* kb = kvh + (size_t)bt * AA * KV_DIM + h * D_HEAD;
    const __half* vb = kb + HIDDEN;

#pragma unroll
    for (int j = 0; j < 4; j++) {
        const int f = tid + 256 * j;
        const int r = f >> 3, c8 = (f & 7) * 8;
        *(uint4*)(sm2 + r * AQ_STR + c8) = *(const uint4*)(qb + (size_t)r * HIDDEN + c8);
        *(uint4*)(sm2 + 128 * AQ_STR + r * AQ_STR + c8) = *(const uint4*)(kb + (size_t)r * KV_DIM + c8);
        *(uint4*)(sm2 + 2 * 128 * AQ_STR + r * AQ_STR + c8) = *(const uint4*)(vb + (size_t)r * KV_DIM + c8);
    }
    __syncthreads();

    const uint32_t aAddr = sq + (((uint32_t)(w * 16) + (lane & 15)) * AQ_STR + (lane >> 4) * 8) * 2;
    const uint32_t kAddr = sk + ((((lane >> 4) & 1) * 8 + (lane & 7)) * AQ_STR + ((lane >> 3) & 1) * 8) * 2;
    const uint32_t vAddr = sv + ((((lane >> 3) & 1) * 8 + (lane & 7)) * AQ_STR + (lane >> 4) * 8) * 2;

    float sacc[16][4];
#pragma unroll
    for (int j = 0; j < 16; j++)
#pragma unroll
        for (int r = 0; r < 4; r++) sacc[j][r] = 0.f;

#pragma unroll
    for (int ks = 0; ks < 4; ks++) {
        const int k0 = ks * 16;
        uint32_t a[4];
        ldsm_x4(a, aAddr + k0 * 2);
#pragma unroll
        for (int p = 0; p < 8; p++) {
            uint32_t bf[4];
            ldsm_x4(bf, kAddr + (p * 16 * AQ_STR + k0) * 2);
            mma_f16(sacc[2 * p],     a, bf);
            mma_f16(sacc[2 * p + 1], a, bf + 2);
        }
    }

    {
        float mx0 = -FLT_MAX, mx1 = -FLT_MAX;
#pragma unroll
        for (int j = 0; j < 16; j++) {
            sacc[j][0] *= 0.125f; sacc[j][1] *= 0.125f;
            sacc[j][2] *= 0.125f; sacc[j][3] *= 0.125f;
            mx0 = fmaxf(mx0, fmaxf(sacc[j][0], sacc[j][1]));
            mx1 = fmaxf(mx1, fmaxf(sacc[j][2], sacc[j][3]));
        }
        mx0 = fmaxf(mx0, __shfl_xor_sync(0xffffffffu, mx0, 1));
        mx0 = fmaxf(mx0, __shfl_xor_sync(0xffffffffu, mx0, 2));
        mx1 = fmaxf(mx1, __shfl_xor_sync(0xffffffffu, mx1, 1));
        mx1 = fmaxf(mx1, __shfl_xor_sync(0xffffffffu, mx1, 2));
        float s0 = 0.f, s1 = 0.f;
#pragma unroll
        for (int j = 0; j < 16; j++) {
            sacc[j][0] = __expf(sacc[j][0] - mx0); s0 += sacc[j][0];
            sacc[j][1] = __expf(sacc[j][1] - mx0); s0 += sacc[j][1];
            sacc[j][2] = __expf(sacc[j][2] - mx1); s1 += sacc[j][2];
            sacc[j][3] = __expf(sacc[j][3] - mx1); s1 += sacc[j][3];
        }
        s0 += __shfl_xor_sync(0xffffffffu, s0, 1);
        s0 += __shfl_xor_sync(0xffffffffu, s0, 2);
        s1 += __shfl_xor_sync(0xffffffffu, s1, 1);
        s1 += __shfl_xor_sync(0xffffffffu, s1, 2);
        const float i0 = 1.0f / s0, i1 = 1.0f / s1;
#pragma unroll
        for (int j = 0; j < 16; j++) {
            sacc[j][0] *= i0; sacc[j][1] *= i0;
            sacc[j][2] *= i1; sacc[j][3] *= i1;
        }
    }

    float oacc[8][4];
#pragma unroll
    for (int j = 0; j < 8; j++)
#pragma unroll
        for (int r = 0; r < 4; r++) oacc[j][r] = 0.f;

#pragma unroll
    for (int t = 0; t < 8; t++) {
        uint32_t pa[4];
        pa[0] = pack_h2(sacc[2 * t][0],     sacc[2 * t][1]);
        pa[1] = pack_h2(sacc[2 * t][2],     sacc[2 * t][3]);
        pa[2] = pack_h2(sacc[2 * t + 1][0], sacc[2 * t + 1][1]);
        pa[3] = pack_h2(sacc[2 * t + 1][2], sacc[2 * t + 1][3]);
#pragma unroll
        for (int p = 0; p < 4; p++) {
            uint32_t bf[4];
            ldsm_x4_t(bf, vAddr + (t * 16 * AQ_STR + p * 16) * 2);
            mma_f16(oacc[2 * p],     pa, bf);
            mma_f16(oacc[2 * p + 1], pa, bf + 2);
        }
    }

    {
        __half* orow0 = ao + ((size_t)bt * HW + qr0 + w * 16 + g) * HIDDEN + h * D_HEAD + 2 * tg;
        __half* orow1 = orow0 + 8 * (size_t)HIDDEN;
#pragma unroll
        for (int j = 0; j < 8; j++) {
            *(uint32_t*)(orow0 + 8 * j) = pack_h2(oacc[j][0], oacc[j][1]);
            *(uint32_t*)(orow1 + 8 * j) = pack_h2(oacc[j][2], oacc[j][3]);
        }
    }
}

// ---------------------------------------------------------------------------
// Launch
// ---------------------------------------------------------------------------
extern "C" void kernel_launch(void* const* d_in, const int* in_sizes, int n_in,
                              void* d_out, int out_size)
{
    const float* x       = (const float*)d_in[0];
    const float* latents = (const float*)d_in[1];
    const float* g1      = (const float*)d_in[2];
    const float* b1      = (const float*)d_in[3];
    const float* g2      = (const float*)d_in[4];
    const float* b2      = (const float*)d_in[5];
    const float* Wq      = (const float*)d_in[6];
    const float* Wkv     = (const float*)d_in[7];
    const float* Wo      = (const float*)d_in[8];
    float* out           = (float*)d_out;

    __half *xnh, *lnh, *qh, *kvh, *aoh, *wqh, *wkvh, *woh;
    cudaGetSymbolAddress((void**)&xnh,  g_xnh);
    cudaGetSymbolAddress((void**)&lnh,  g_lnh);
    cudaGetSymbolAddress((void**)&qh,   g_qh);
    cudaGetSymbolAddress((void**)&kvh,  g_kvh);
    cudaGetSymbolAddress((void**)&aoh,  g_aoh);
    cudaGetSymbolAddress((void**)&wqh,  g_wqh);
    cudaGetSymbolAddress((void**)&wkvh, g_wkvh);
    cudaGetSymbolAddress((void**)&woh,  g_woh);

    cudaFuncSetAttribute(gemm_qkv,        cudaFuncAttributeMaxDynamicSharedMemorySize, G2_SMEM);
    cudaFuncSetAttribute(gemm_one<float>, cudaFuncAttributeMaxDynamicSharedMemorySize, G2_SMEM);
    cudaFuncSetAttribute(attn2_kernel,    cudaFuncAttributeMaxDynamicSharedMemorySize, ATTN2_SMEM);

    prep_kernel<<<PREP_BLKS, 256>>>(Wq, wqh, Wkv, wkvh, Wo, woh,
                                    x, latents, g1, b1, g2, b2, xnh, lnh);

    gemm_qkv<<<QK_SPLIT + (ROWS_X / 128) * (KV_DIM / 128), GTHREADS, G2_SMEM>>>(
        lnh, wqh, qh, xnh, wkvh, kvh);

    attn2_kernel<<<dim3(HW / 128, N_HEADS, BT), 256, ATTN2_SMEM>>>(qh, kvh, aoh);

    gemm_one<float><<<dim3(ROWS_L / 128, C_DIM / 128), GTHREADS, G2_SMEM>>>(aoh, woh, out, C_DIM, HIDDEN);
}

// round 16
// speedup vs baseline: 1.1727x; 1.1727x over previous
#include <cuda_runtime.h>
#include <cuda_fp16.h>
#include <cstdint>
#include <cfloat>

// ---------------------------------------------------------------------------
// Problem dims (fixed)
// ---------------------------------------------------------------------------
#define C_DIM   3072
#define HIDDEN  3072
#define KV_DIM  6144
#define N_HEADS 48
#define D_HEAD  64
#define BT      4
#define AA      128
#define HW      1024
#define ROWS_X  (BT * AA)    // 512
#define ROWS_L  (BT * HW)    // 4096

// ---------------------------------------------------------------------------
// Scratch (device globals: allocation-free rule)
// ---------------------------------------------------------------------------
__device__ __half g_xnh[ROWS_X * C_DIM];
__device__ __half g_lnh[ROWS_L * C_DIM];
__device__ __half g_qh [ROWS_L * HIDDEN];
__device__ __half g_kvh[ROWS_X * KV_DIM];
__device__ __half g_aoh[ROWS_L * HIDDEN];
__device__ __half g_wqh [C_DIM * HIDDEN];   // Wq  half [K=3072][N=3072] (orig layout)
__device__ __half g_wkvh[C_DIM * KV_DIM];   // Wkv half [K=3072][N=6144]
__device__ __half g_woh [HIDDEN * C_DIM];   // Wo  half [K=3072][N=3072]

// ---------------------------------------------------------------------------
// Helpers (sm_100-safe: mma.sync fp16 + ldmatrix + cp.async only)
// ---------------------------------------------------------------------------
__device__ __forceinline__ void mma_f16(float* c, const uint32_t* a, const uint32_t* b) {
    asm volatile(
        "mma.sync.aligned.m16n8k16.row.col.f32.f16.f16.f32 "
        "{%0,%1,%2,%3}, {%4,%5,%6,%7}, {%8,%9}, {%0,%1,%2,%3};\n"
        : "+f"(c[0]), "+f"(c[1]), "+f"(c[2]), "+f"(c[3])
        : "r"(a[0]), "r"(a[1]), "r"(a[2]), "r"(a[3]), "r"(b[0]), "r"(b[1]));
}

__device__ __forceinline__ void ldsm_x4(uint32_t* r, uint32_t addr) {
    asm volatile(
        "ldmatrix.sync.aligned.m8n8.x4.shared.b16 {%0,%1,%2,%3}, [%4];\n"
        : "=r"(r[0]), "=r"(r[1]), "=r"(r[2]), "=r"(r[3]) : "r"(addr));
}

__device__ __forceinline__ void ldsm_x4_t(uint32_t* r, uint32_t addr) {
    asm volatile(
        "ldmatrix.sync.aligned.m8n8.x4.trans.shared.b16 {%0,%1,%2,%3}, [%4];\n"
        : "=r"(r[0]), "=r"(r[1]), "=r"(r[2]), "=r"(r[3]) : "r"(addr));
}

__device__ __forceinline__ uint32_t smem_u32(const void* p) {
    uint32_t a;
    asm("{ .reg .u64 t; cvta.to.shared.u64 t, %1; cvt.u32.u64 %0, t; }" : "=r"(a) : "l"(p));
    return a;
}

__device__ __forceinline__ void cpa16(uint32_t dst, const void* src) {
    asm volatile("cp.async.cg.shared.global [%0], [%1], 16;\n" :: "r"(dst), "l"(src) : "memory");
}
#define CP_COMMIT() asm volatile("cp.async.commit_group;\n" ::: "memory")
#define CP_WAIT1()  asm volatile("cp.async.wait_group 1;\n" ::: "memory")

__device__ __forceinline__ uint32_t pack_h2(float a, float b) {
    __half2 h = __floats2half2_rn(a, b);
    return *(uint32_t*)&h;
}

// ---------------------------------------------------------------------------
// Fused prep: weight fp32->fp16 converts + both LayerNorms, one launch.
// ---------------------------------------------------------------------------
#define CVT_WQ_BLKS  ((C_DIM * HIDDEN) / 2048)            // 4608
#define CVT_WKV_BLKS ((C_DIM * KV_DIM) / 2048)            // 9216
#define CVT_WO_BLKS  ((HIDDEN * C_DIM) / 2048)            // 4608
#define CVT_TOTAL    (CVT_WQ_BLKS + CVT_WKV_BLKS + CVT_WO_BLKS)   // 18432
#define PREP_BLKS    (CVT_TOTAL + ROWS_X + ROWS_L)                // 23040

__global__ __launch_bounds__(256)
void prep_kernel(const float* __restrict__ Wq,  __half* __restrict__ wqh,
                 const float* __restrict__ Wkv, __half* __restrict__ wkvh,
                 const float* __restrict__ Wo,  __half* __restrict__ woh,
                 const float* __restrict__ x, const float* __restrict__ latents,
                 const float* __restrict__ g1, const float* __restrict__ b1,
                 const float* __restrict__ g2, const float* __restrict__ b2,
                 __half* __restrict__ xn, __half* __restrict__ lnout)
{
    const int tid = threadIdx.x;
    if (blockIdx.x < CVT_TOTAL) {
        int bx = blockIdx.x;
        const float* in;
        __half* out;
        if (bx < CVT_WQ_BLKS)                      { in = Wq;  out = wqh; }
        else if (bx < CVT_WQ_BLKS + CVT_WKV_BLKS)  { bx -= CVT_WQ_BLKS;  in = Wkv; out = wkvh; }
        else                                       { bx -= CVT_WQ_BLKS + CVT_WKV_BLKS; in = Wo; out = woh; }
        const size_t i = ((size_t)bx * 256 + tid) * 8;
        float4 v0 = *(const float4*)(in + i);
        float4 v1 = *(const float4*)(in + i + 4);
        uint4 o;
        o.x = pack_h2(v0.x, v0.y); o.y = pack_h2(v0.z, v0.w);
        o.z = pack_h2(v1.x, v1.y); o.w = pack_h2(v1.z, v1.w);
        *(uint4*)(out + i) = o;
        return;
    }

    const int row = blockIdx.x - CVT_TOTAL;
    const bool isx = row < ROWS_X;
    const float* xr = isx ? x + (size_t)row * C_DIM
                          : latents + (size_t)(row - ROWS_X) * C_DIM;
    const float* gamma = isx ? g1 : g2;
    const float* beta  = isx ? b1 : b2;
    __half* yr = isx ? xn + (size_t)row * C_DIM
                     : lnout + (size_t)(row - ROWS_X) * C_DIM;

    float4 v[3];
    float s = 0.f, s2 = 0.f;
#pragma unroll
    for (int j = 0; j < 3; j++) {
        v[j] = *(const float4*)(xr + (size_t)(tid + 256 * j) * 4);
        s  += v[j].x + v[j].y + v[j].z + v[j].w;
        s2 += v[j].x*v[j].x + v[j].y*v[j].y + v[j].z*v[j].z + v[j].w*v[j].w;
    }
#pragma unroll
    for (int o = 16; o > 0; o >>= 1) {
        s  += __shfl_xor_sync(0xffffffffu, s, o);
        s2 += __shfl_xor_sync(0xffffffffu, s2, o);
    }
    __shared__ float red[2][8];
    const int w = tid >> 5, lane = tid & 31;
    if (lane == 0) { red[0][w] = s; red[1][w] = s2; }
    __syncthreads();
    float ts = 0.f, ts2 = 0.f;
#pragma unroll
    for (int i = 0; i < 8; i++) { ts += red[0][i]; ts2 += red[1][i]; }
    const float mean = ts * (1.0f / C_DIM);
    const float var  = ts2 * (1.0f / C_DIM) - mean * mean;
    const float rstd = rsqrtf(var + 1e-5f);

#pragma unroll
    for (int j = 0; j < 3; j++) {
        const int c4 = (tid + 256 * j) * 4;
        float4 g = *(const float4*)(gamma + c4);
        float4 b = *(const float4*)(beta  + c4);
        uint2 o;
        o.x = pack_h2((v[j].x - mean) * rstd * g.x + b.x,
                      (v[j].y - mean) * rstd * g.y + b.y);
        o.y = pack_h2((v[j].z - mean) * rstd * g.z + b.z,
                      (v[j].w - mean) * rstd * g.w + b.w);
        *(uint2*)(yr + c4) = o;
    }
}

// ---------------------------------------------------------------------------
// FP16 GEMM (R14-proven config): 128x128 block, 256 threads (2m x 4n warps,
// warp tile 64x32), BKT=64, 3-stage cp.async, 2 CTAs/SM, regs=128 cap.
// De-burst v2: A-fill after k-step 0, B-fill after k-step 16.
// C[M,N] = A[M,K] half (row-major) * B[K,N] half (row-major). N%128, K%64 == 0.
// ---------------------------------------------------------------------------
#define BKT 64
#define A_STRH 72
#define B_STRH 136
#define ASTG_B (128 * A_STRH * 2)        // 18432 B
#define BSTG_B (64 * B_STRH * 2)         // 17408 B
#define G2_SMEM (3 * (ASTG_B + BSTG_B))  // 107520 B

template <typename OutT>
__device__ __forceinline__ void gemm_tile(const __half* __restrict__ A,
                                          const __half* __restrict__ B,
                                          OutT* __restrict__ C,
                                          int m0, int n0, int N, int K)
{
    extern __shared__ __half smh[];
    const uint32_t sbase = smem_u32(smh);

    const int tid  = threadIdx.x;
    const int lane = tid & 31;
    const int w    = tid >> 5;
    const int wm   = w >> 2;
    const int wn   = w & 3;
    const int g    = lane >> 2;
    const int tg   = lane & 3;

    const int nk = K / BKT;

    const uint32_t a_row = (uint32_t)(wm * 64) + ((lane >> 3) & 1) * 8 + (lane & 7);
    const uint32_t a_col = (uint32_t)(lane >> 4) * 8;
    const uint32_t b_krow = (uint32_t)(((lane >> 3) & 1) * 8 + (lane & 7));
    const uint32_t b_noff = (uint32_t)(lane >> 4) * 8;

    auto fillA = [&](int s, int kc) {
        const uint32_t aoff = sbase + (uint32_t)s * ASTG_B;
#pragma unroll
        for (int j = 0; j < 4; j++) {
            const int f = tid + 256 * j;
            const int row = f >> 3, ch = f & 7;
            cpa16(aoff + row * (A_STRH * 2) + ch * 16,
                  A + (size_t)(m0 + row) * K + kc + ch * 8);
        }
    };
    auto fillB = [&](int s, int kc) {
        const uint32_t boff = sbase + 3 * ASTG_B + (uint32_t)s * BSTG_B;
#pragma unroll
        for (int j = 0; j < 4; j++) {
            const int f = tid + 256 * j;
            const int row = f >> 4, ch = f & 15;
            cpa16(boff + row * (B_STRH * 2) + ch * 16,
                  B + (size_t)(kc + row) * N + n0 + ch * 8);
        }
    };

    float acc[4][4][4];
#pragma unroll
    for (int mi = 0; mi < 4; mi++)
#pragma unroll
        for (int ni = 0; ni < 4; ni++)
#pragma unroll
            for (int r = 0; r < 4; r++) acc[mi][ni][r] = 0.f;

    fillA(0, 0);   fillB(0, 0);   CP_COMMIT();
    fillA(1, BKT); fillB(1, BKT); CP_COMMIT();

    for (int kt = 0; kt < nk; ++kt) {
        CP_WAIT1();
        __syncthreads();

        const int s = kt % 3;
        const uint32_t aBase = sbase + (uint32_t)s * ASTG_B + (a_row * A_STRH + a_col) * 2;
        const uint32_t bBase = sbase + 3 * ASTG_B + (uint32_t)s * BSTG_B
                             + (b_krow * B_STRH + (uint32_t)(wn * 32) + b_noff) * 2;

        // one k-step: B ldsm first (first MMA's last-arriving operand), then A
        auto kstep = [&](int k0) {
            uint32_t a[4][4], bf[8];
            ldsm_x4_t(bf,     bBase + (k0 * B_STRH) * 2);
            ldsm_x4_t(bf + 4, bBase + (k0 * B_STRH + 16) * 2);
#pragma unroll
            for (int mi = 0; mi < 4; mi++)
                ldsm_x4(a[mi], aBase + (mi * 16 * A_STRH + k0) * 2);
#pragma unroll
            for (int mi = 0; mi < 4; mi++)
#pragma unroll
                for (int ni = 0; ni < 4; ni++)
                    mma_f16(acc[mi][ni], a[mi], bf + ni * 2);
        };

        const bool more = (kt + 2 < nk);
        const int  s2   = (kt + 2) % 3;

        kstep(0);                                // LSU serves LDSMs alone
        if (more) fillA(s2, (kt + 2) * BKT);     // A-half of prefetch
        kstep(16);
        if (more) fillB(s2, (kt + 2) * BKT);     // B-half of prefetch
        CP_COMMIT();                             // one group per iter (empty on tail)
        kstep(32);
        kstep(48);
    }

#pragma unroll
    for (int mi = 0; mi < 4; mi++) {
        const int r = m0 + wm * 64 + mi * 16 + g;
#pragma unroll
        for (int ni = 0; ni < 4; ni++) {
            const int c = n0 + wn * 32 + ni * 8 + 2 * tg;
            if constexpr (sizeof(OutT) == 4) {
                *(float2*)&C[(size_t)r * N + c]       = make_float2(acc[mi][ni][0], acc[mi][ni][1]);
                *(float2*)&C[(size_t)(r + 8) * N + c] = make_float2(acc[mi][ni][2], acc[mi][ni][3]);
            } else {
                *(uint32_t*)&C[(size_t)r * N + c]       = pack_h2(acc[mi][ni][0], acc[mi][ni][1]);
                *(uint32_t*)&C[(size_t)(r + 8) * N + c] = pack_h2(acc[mi][ni][2], acc[mi][ni][3]);
            }
        }
    }
}

// Fused Wq + Wkv launch: 1D grid, CTAs [0,768) -> q GEMM, [768,960) -> kv GEMM.
#define QK_SPLIT 768
__global__ __launch_bounds__(256, 2)
void gemm_qkv(const __half* __restrict__ ln, const __half* __restrict__ wq,
              __half* __restrict__ q,
              const __half* __restrict__ xn, const __half* __restrict__ wkv,
              __half* __restrict__ kv)
{
    const int bx = blockIdx.x;
    if (bx < QK_SPLIT) {
        gemm_tile<__half>(ln, wq, q, (bx & 31) * 128, (bx >> 5) * 128, HIDDEN, C_DIM);
    } else {
        const int t = bx - QK_SPLIT;
        gemm_tile<__half>(xn, wkv, kv, (t & 3) * 128, (t >> 2) * 128, KV_DIM, C_DIM);
    }
}

// Plain single GEMM (Wo)
template <typename OutT>
__global__ __launch_bounds__(256, 2)
void gemm_one(const __half* __restrict__ A, const __half* __restrict__ B,
              OutT* __restrict__ C, int N, int K)
{
    gemm_tile<OutT>(A, B, C, blockIdx.x * 128, blockIdx.y * 128, N, K);
}

// ---------------------------------------------------------------------------
// Attention v3 (R13/R14-proven): tensor-core QK^T + PV, register softmax.
// V staged as-is ([key][d]); PV B-frags via ldmatrix.trans.
// ---------------------------------------------------------------------------
#define AQ_STR 72
#define ATTN2_SMEM (3 * 128 * AQ_STR * 2)   // 55296 B

__global__ __launch_bounds__(256, 2)
void attn2_kernel(const __half* __restrict__ qh, const __half* __restrict__ kvh,
                  __half* __restrict__ ao)
{
    extern __shared__ __half sm2[];
    const uint32_t sq = smem_u32(sm2);
    const uint32_t sk = sq + 128 * AQ_STR * 2;
    const uint32_t sv = sk + 128 * AQ_STR * 2;

    const int tid  = threadIdx.x;
    const int lane = tid & 31;
    const int w    = tid >> 5;
    const int g    = lane >> 2;
    const int tg   = lane & 3;
    const int cq   = blockIdx.x;
    const int h    = blockIdx.y;
    const int bt   = blockIdx.z;
    const int qr0  = cq * 128;

    const __half* qb = qh  + ((size_t)bt * HW + qr0) * HIDDEN + h * D_HEAD;
    const __half* kb = kvh + (size_t)bt * AA * KV_DIM + h * D_HEAD;
    const __half* vb = kb + HIDDEN;

#pragma unroll
    for (int j = 0; j < 4; j++) {
        const int f = tid + 256 * j;
        const int r = f >> 3, c8 = (f & 7) * 8;
        *(uint4*)(sm2 + r * AQ_STR + c8) = *(const uint4*)(qb + (size_t)r * HIDDEN + c8);
        *(uint4*)(sm2 + 128 * AQ_STR + r * AQ_STR + c8) = *(const uint4*)(kb + (size_t)r * KV_DIM + c8);
        *(uint4*)(sm2 + 2 * 128 * AQ_STR + r * AQ_STR + c8) = *(const uint4*)(vb + (size_t)r * KV_DIM + c8);
    }
    __syncthreads();

    const uint32_t aAddr = sq + (((uint32_t)(w * 16) + (lane & 15)) * AQ_STR + (lane >> 4) * 8) * 2;
    const uint32_t kAddr = sk + ((((lane >> 4) & 1) * 8 + (lane & 7)) * AQ_STR + ((lane >> 3) & 1) * 8) * 2;
    const uint32_t vAddr = sv + ((((lane >> 3) & 1) * 8 + (lane & 7)) * AQ_STR + (lane >> 4) * 8) * 2;

    float sacc[16][4];
#pragma unroll
    for (int j = 0; j < 16; j++)
#pragma unroll
        for (int r = 0; r < 4; r++) sacc[j][r] = 0.f;

#pragma unroll
    for (int ks = 0; ks < 4; ks++) {
        const int k0 = ks * 16;
        uint32_t a[4];
        ldsm_x4(a, aAddr + k0 * 2);
#pragma unroll
        for (int p = 0; p < 8; p++) {
            uint32_t bf[4];
            ldsm_x4(bf, kAddr + (p * 16 * AQ_STR + k0) * 2);
            mma_f16(sacc[2 * p],     a, bf);
            mma_f16(sacc[2 * p + 1], a, bf + 2);
        }
    }

    {
        float mx0 = -FLT_MAX, mx1 = -FLT_MAX;
#pragma unroll
        for (int j = 0; j < 16; j++) {
            sacc[j][0] *= 0.125f; sacc[j][1] *= 0.125f;
            sacc[j][2] *= 0.125f; sacc[j][3] *= 0.125f;
            mx0 = fmaxf(mx0, fmaxf(sacc[j][0], sacc[j][1]));
            mx1 = fmaxf(mx1, fmaxf(sacc[j][2], sacc[j][3]));
        }
        mx0 = fmaxf(mx0, __shfl_xor_sync(0xffffffffu, mx0, 1));
        mx0 = fmaxf(mx0, __shfl_xor_sync(0xffffffffu, mx0, 2));
        mx1 = fmaxf(mx1, __shfl_xor_sync(0xffffffffu, mx1, 1));
        mx1 = fmaxf(mx1, __shfl_xor_sync(0xffffffffu, mx1, 2));
        float s0 = 0.f, s1 = 0.f;
#pragma unroll
        for (int j = 0; j < 16; j++) {
            sacc[j][0] = __expf(sacc[j][0] - mx0); s0 += sacc[j][0];
            sacc[j][1] = __expf(sacc[j][1] - mx0); s0 += sacc[j][1];
            sacc[j][2] = __expf(sacc[j][2] - mx1); s1 += sacc[j][2];
            sacc[j][3] = __expf(sacc[j][3] - mx1); s1 += sacc[j][3];
        }
        s0 += __shfl_xor_sync(0xffffffffu, s0, 1);
        s0 += __shfl_xor_sync(0xffffffffu, s0, 2);
        s1 += __shfl_xor_sync(0xffffffffu, s1, 1);
        s1 += __shfl_xor_sync(0xffffffffu, s1, 2);
        const float i0 = 1.0f / s0, i1 = 1.0f / s1;
#pragma unroll
        for (int j = 0; j < 16; j++) {
            sacc[j][0] *= i0; sacc[j][1] *= i0;
            sacc[j][2] *= i1; sacc[j][3] *= i1;
        }
    }

    float oacc[8][4];
#pragma unroll
    for (int j = 0; j < 8; j++)
#pragma unroll
        for (int r = 0; r < 4; r++) oacc[j][r] = 0.f;

#pragma unroll
    for (int t = 0; t < 8; t++) {
        uint32_t pa[4];
        pa[0] = pack_h2(sacc[2 * t][0],     sacc[2 * t][1]);
        pa[1] = pack_h2(sacc[2 * t][2],     sacc[2 * t][3]);
        pa[2] = pack_h2(sacc[2 * t + 1][0], sacc[2 * t + 1][1]);
        pa[3] = pack_h2(sacc[2 * t + 1][2], sacc[2 * t + 1][3]);
#pragma unroll
        for (int p = 0; p < 4; p++) {
            uint32_t bf[4];
            ldsm_x4_t(bf, vAddr + (t * 16 * AQ_STR + p * 16) * 2);
            mma_f16(oacc[2 * p],     pa, bf);
            mma_f16(oacc[2 * p + 1], pa, bf + 2);
        }
    }

    {
        __half* orow0 = ao + ((size_t)bt * HW + qr0 + w * 16 + g) * HIDDEN + h * D_HEAD + 2 * tg;
        __half* orow1 = orow0 + 8 * (size_t)HIDDEN;
#pragma unroll
        for (int j = 0; j < 8; j++) {
            *(uint32_t*)(orow0 + 8 * j) = pack_h2(oacc[j][0], oacc[j][1]);
            *(uint32_t*)(orow1 + 8 * j) = pack_h2(oacc[j][2], oacc[j][3]);
        }
    }
}

// ---------------------------------------------------------------------------
// Launch
// ---------------------------------------------------------------------------
extern "C" void kernel_launch(void* const* d_in, const int* in_sizes, int n_in,
                              void* d_out, int out_size)
{
    const float* x       = (const float*)d_in[0];
    const float* latents = (const float*)d_in[1];
    const float* g1      = (const float*)d_in[2];
    const float* b1      = (const float*)d_in[3];
    const float* g2      = (const float*)d_in[4];
    const float* b2      = (const float*)d_in[5];
    const float* Wq      = (const float*)d_in[6];
    const float* Wkv     = (const float*)d_in[7];
    const float* Wo      = (const float*)d_in[8];
    float* out           = (float*)d_out;

    __half *xnh, *lnh, *qh, *kvh, *aoh, *wqh, *wkvh, *woh;
    cudaGetSymbolAddress((void**)&xnh,  g_xnh);
    cudaGetSymbolAddress((void**)&lnh,  g_lnh);
    cudaGetSymbolAddress((void**)&qh,   g_qh);
    cudaGetSymbolAddress((void**)&kvh,  g_kvh);
    cudaGetSymbolAddress((void**)&aoh,  g_aoh);
    cudaGetSymbolAddress((void**)&wqh,  g_wqh);
    cudaGetSymbolAddress((void**)&wkvh, g_wkvh);
    cudaGetSymbolAddress((void**)&woh,  g_woh);

    cudaFuncSetAttribute(gemm_qkv,        cudaFuncAttributeMaxDynamicSharedMemorySize, G2_SMEM);
    cudaFuncSetAttribute(gemm_one<float>, cudaFuncAttributeMaxDynamicSharedMemorySize, G2_SMEM);
    cudaFuncSetAttribute(attn2_kernel,    cudaFuncAttributeMaxDynamicSharedMemorySize, ATTN2_SMEM);

    prep_kernel<<<PREP_BLKS, 256>>>(Wq, wqh, Wkv, wkvh, Wo, woh,
                                    x, latents, g1, b1, g2, b2, xnh, lnh);

    gemm_qkv<<<QK_SPLIT + (ROWS_X / 128) * (KV_DIM / 128), 256, G2_SMEM>>>(
        lnh, wqh, qh, xnh, wkvh, kvh);

    attn2_kernel<<<dim3(HW / 128, N_HEADS, BT), 256, ATTN2_SMEM>>>(qh, kvh, aoh);

    gemm_one<float><<<dim3(ROWS_L / 128, C_DIM / 128), 256, G2_SMEM>>>(aoh, woh, out, C_DIM, HIDDEN);
}

// round 17
// speedup vs baseline: 1.1845x; 1.0101x over previous
#include <cuda_runtime.h>
#include <cuda_fp16.h>
#include <cstdint>
#include <cfloat>

// ---------------------------------------------------------------------------
// Problem dims (fixed)
// ---------------------------------------------------------------------------
#define C_DIM   3072
#define HIDDEN  3072
#define KV_DIM  6144
#define N_HEADS 48
#define D_HEAD  64
#define BT      4
#define AA      128
#define HW      1024
#define ROWS_X  (BT * AA)    // 512
#define ROWS_L  (BT * HW)    // 4096

// ---------------------------------------------------------------------------
// Scratch (device globals: allocation-free rule)
// ---------------------------------------------------------------------------
__device__ __half g_xnh[ROWS_X * C_DIM];
__device__ __half g_lnh[ROWS_L * C_DIM];
__device__ __half g_qh [ROWS_L * HIDDEN];
__device__ __half g_kvh[ROWS_X * KV_DIM];
__device__ __half g_aoh[ROWS_L * HIDDEN];
__device__ __half g_wqh [C_DIM * HIDDEN];   // Wq  half [K=3072][N=3072] (orig layout)
__device__ __half g_wkvh[C_DIM * KV_DIM];   // Wkv half [K=3072][N=6144]
__device__ __half g_woh [HIDDEN * C_DIM];   // Wo  half [K=3072][N=3072]

// ---------------------------------------------------------------------------
// Helpers (sm_100-safe: mma.sync fp16 + ldmatrix + cp.async only)
// ---------------------------------------------------------------------------
__device__ __forceinline__ void mma_f16(float* c, const uint32_t* a, const uint32_t* b) {
    asm volatile(
        "mma.sync.aligned.m16n8k16.row.col.f32.f16.f16.f32 "
        "{%0,%1,%2,%3}, {%4,%5,%6,%7}, {%8,%9}, {%0,%1,%2,%3};\n"
        : "+f"(c[0]), "+f"(c[1]), "+f"(c[2]), "+f"(c[3])
        : "r"(a[0]), "r"(a[1]), "r"(a[2]), "r"(a[3]), "r"(b[0]), "r"(b[1]));
}

__device__ __forceinline__ void ldsm_x4(uint32_t* r, uint32_t addr) {
    asm volatile(
        "ldmatrix.sync.aligned.m8n8.x4.shared.b16 {%0,%1,%2,%3}, [%4];\n"
        : "=r"(r[0]), "=r"(r[1]), "=r"(r[2]), "=r"(r[3]) : "r"(addr));
}

__device__ __forceinline__ void ldsm_x4_t(uint32_t* r, uint32_t addr) {
    asm volatile(
        "ldmatrix.sync.aligned.m8n8.x4.trans.shared.b16 {%0,%1,%2,%3}, [%4];\n"
        : "=r"(r[0]), "=r"(r[1]), "=r"(r[2]), "=r"(r[3]) : "r"(addr));
}

__device__ __forceinline__ uint32_t smem_u32(const void* p) {
    uint32_t a;
    asm("{ .reg .u64 t; cvta.to.shared.u64 t, %1; cvt.u32.u64 %0, t; }" : "=r"(a) : "l"(p));
    return a;
}

__device__ __forceinline__ void cpa16(uint32_t dst, const void* src) {
    asm volatile("cp.async.cg.shared.global [%0], [%1], 16;\n" :: "r"(dst), "l"(src) : "memory");
}
#define CP_COMMIT() asm volatile("cp.async.commit_group;\n" ::: "memory")
#define CP_WAIT1()  asm volatile("cp.async.wait_group 1;\n" ::: "memory")

__device__ __forceinline__ uint32_t pack_h2(float a, float b) {
    __half2 h = __floats2half2_rn(a, b);
    return *(uint32_t*)&h;
}

__device__ __forceinline__ float ex2(float x) {
    float y;
    asm("ex2.approx.f32 %0, %1;" : "=f"(y) : "f"(x));
    return y;
}

// ---------------------------------------------------------------------------
// Shared convert block body: 2048 fp32 -> fp16 per block
// ---------------------------------------------------------------------------
__device__ __forceinline__ void cvt_block(const float* __restrict__ in,
                                          __half* __restrict__ out,
                                          int bx, int tid)
{
    const size_t i = ((size_t)bx * 256 + tid) * 8;
    float4 v0 = *(const float4*)(in + i);
    float4 v1 = *(const float4*)(in + i + 4);
    uint4 o;
    o.x = pack_h2(v0.x, v0.y); o.y = pack_h2(v0.z, v0.w);
    o.z = pack_h2(v1.x, v1.y); o.w = pack_h2(v1.z, v1.w);
    *(uint4*)(out + i) = o;
}

// ---------------------------------------------------------------------------
// Prep: Wq + Wkv converts + both LayerNorms (Wo convert moved to gemm_qkv tail)
// ---------------------------------------------------------------------------
#define CVT_WQ_BLKS  ((C_DIM * HIDDEN) / 2048)            // 4608
#define CVT_WKV_BLKS ((C_DIM * KV_DIM) / 2048)            // 9216
#define CVT_WO_BLKS  ((HIDDEN * C_DIM) / 2048)            // 4608
#define CVT_QKV      (CVT_WQ_BLKS + CVT_WKV_BLKS)         // 13824
#define PREP_BLKS    (CVT_QKV + ROWS_X + ROWS_L)          // 18432

__global__ __launch_bounds__(256)
void prep_kernel(const float* __restrict__ Wq,  __half* __restrict__ wqh,
                 const float* __restrict__ Wkv, __half* __restrict__ wkvh,
                 const float* __restrict__ x, const float* __restrict__ latents,
                 const float* __restrict__ g1, const float* __restrict__ b1,
                 const float* __restrict__ g2, const float* __restrict__ b2,
                 __half* __restrict__ xn, __half* __restrict__ lnout)
{
    const int tid = threadIdx.x;
    if (blockIdx.x < CVT_QKV) {
        int bx = blockIdx.x;
        if (bx < CVT_WQ_BLKS) cvt_block(Wq, wqh, bx, tid);
        else                  cvt_block(Wkv, wkvh, bx - CVT_WQ_BLKS, tid);
        return;
    }

    const int row = blockIdx.x - CVT_QKV;
    const bool isx = row < ROWS_X;
    const float* xr = isx ? x + (size_t)row * C_DIM
                          : latents + (size_t)(row - ROWS_X) * C_DIM;
    const float* gamma = isx ? g1 : g2;
    const float* beta  = isx ? b1 : b2;
    __half* yr = isx ? xn + (size_t)row * C_DIM
                     : lnout + (size_t)(row - ROWS_X) * C_DIM;

    float4 v[3];
    float s = 0.f, s2 = 0.f;
#pragma unroll
    for (int j = 0; j < 3; j++) {
        v[j] = *(const float4*)(xr + (size_t)(tid + 256 * j) * 4);
        s  += v[j].x + v[j].y + v[j].z + v[j].w;
        s2 += v[j].x*v[j].x + v[j].y*v[j].y + v[j].z*v[j].z + v[j].w*v[j].w;
    }
#pragma unroll
    for (int o = 16; o > 0; o >>= 1) {
        s  += __shfl_xor_sync(0xffffffffu, s, o);
        s2 += __shfl_xor_sync(0xffffffffu, s2, o);
    }
    __shared__ float red[2][8];
    const int w = tid >> 5, lane = tid & 31;
    if (lane == 0) { red[0][w] = s; red[1][w] = s2; }
    __syncthreads();
    float ts = 0.f, ts2 = 0.f;
#pragma unroll
    for (int i = 0; i < 8; i++) { ts += red[0][i]; ts2 += red[1][i]; }
    const float mean = ts * (1.0f / C_DIM);
    const float var  = ts2 * (1.0f / C_DIM) - mean * mean;
    const float rstd = rsqrtf(var + 1e-5f);

#pragma unroll
    for (int j = 0; j < 3; j++) {
        const int c4 = (tid + 256 * j) * 4;
        float4 g = *(const float4*)(gamma + c4);
        float4 b = *(const float4*)(beta  + c4);
        uint2 o;
        o.x = pack_h2((v[j].x - mean) * rstd * g.x + b.x,
                      (v[j].y - mean) * rstd * g.y + b.y);
        o.y = pack_h2((v[j].z - mean) * rstd * g.z + b.z,
                      (v[j].w - mean) * rstd * g.w + b.w);
        *(uint2*)(yr + c4) = o;
    }
}

// ---------------------------------------------------------------------------
// FP16 GEMM (R16-proven): 128x128 block, 256 threads (2m x 4n warps, warp tile
// 64x32), BKT=64, 3-stage cp.async, 2 CTAs/SM, regs=128 cap.
// De-burst: A-fill after k-step 0, B-fill after k-step 16.
// ---------------------------------------------------------------------------
#define BKT 64
#define A_STRH 72
#define B_STRH 136
#define ASTG_B (128 * A_STRH * 2)        // 18432 B
#define BSTG_B (64 * B_STRH * 2)         // 17408 B
#define G2_SMEM (3 * (ASTG_B + BSTG_B))  // 107520 B

template <typename OutT>
__device__ __forceinline__ void gemm_tile(const __half* __restrict__ A,
                                          const __half* __restrict__ B,
                                          OutT* __restrict__ C,
                                          int m0, int n0, int N, int K)
{
    extern __shared__ __half smh[];
    const uint32_t sbase = smem_u32(smh);

    const int tid  = threadIdx.x;
    const int lane = tid & 31;
    const int w    = tid >> 5;
    const int wm   = w >> 2;
    const int wn   = w & 3;
    const int g    = lane >> 2;
    const int tg   = lane & 3;

    const int nk = K / BKT;

    const uint32_t a_row = (uint32_t)(wm * 64) + ((lane >> 3) & 1) * 8 + (lane & 7);
    const uint32_t a_col = (uint32_t)(lane >> 4) * 8;
    const uint32_t b_krow = (uint32_t)(((lane >> 3) & 1) * 8 + (lane & 7));
    const uint32_t b_noff = (uint32_t)(lane >> 4) * 8;

    auto fillA = [&](int s, int kc) {
        const uint32_t aoff = sbase + (uint32_t)s * ASTG_B;
#pragma unroll
        for (int j = 0; j < 4; j++) {
            const int f = tid + 256 * j;
            const int row = f >> 3, ch = f & 7;
            cpa16(aoff + row * (A_STRH * 2) + ch * 16,
                  A + (size_t)(m0 + row) * K + kc + ch * 8);
        }
    };
    auto fillB = [&](int s, int kc) {
        const uint32_t boff = sbase + 3 * ASTG_B + (uint32_t)s * BSTG_B;
#pragma unroll
        for (int j = 0; j < 4; j++) {
            const int f = tid + 256 * j;
            const int row = f >> 4, ch = f & 15;
            cpa16(boff + row * (B_STRH * 2) + ch * 16,
                  B + (size_t)(kc + row) * N + n0 + ch * 8);
        }
    };

    float acc[4][4][4];
#pragma unroll
    for (int mi = 0; mi < 4; mi++)
#pragma unroll
        for (int ni = 0; ni < 4; ni++)
#pragma unroll
            for (int r = 0; r < 4; r++) acc[mi][ni][r] = 0.f;

    fillA(0, 0);   fillB(0, 0);   CP_COMMIT();
    fillA(1, BKT); fillB(1, BKT); CP_COMMIT();

    for (int kt = 0; kt < nk; ++kt) {
        CP_WAIT1();
        __syncthreads();

        const int s = kt % 3;
        const uint32_t aBase = sbase + (uint32_t)s * ASTG_B + (a_row * A_STRH + a_col) * 2;
        const uint32_t bBase = sbase + 3 * ASTG_B + (uint32_t)s * BSTG_B
                             + (b_krow * B_STRH + (uint32_t)(wn * 32) + b_noff) * 2;

        auto kstep = [&](int k0) {
            uint32_t a[4][4], bf[8];
            ldsm_x4_t(bf,     bBase + (k0 * B_STRH) * 2);
            ldsm_x4_t(bf + 4, bBase + (k0 * B_STRH + 16) * 2);
#pragma unroll
            for (int mi = 0; mi < 4; mi++)
                ldsm_x4(a[mi], aBase + (mi * 16 * A_STRH + k0) * 2);
#pragma unroll
            for (int mi = 0; mi < 4; mi++)
#pragma unroll
                for (int ni = 0; ni < 4; ni++)
                    mma_f16(acc[mi][ni], a[mi], bf + ni * 2);
        };

        const bool more = (kt + 2 < nk);
        const int  s2   = (kt + 2) % 3;

        kstep(0);
        if (more) fillA(s2, (kt + 2) * BKT);
        kstep(16);
        if (more) fillB(s2, (kt + 2) * BKT);
        CP_COMMIT();
        kstep(32);
        kstep(48);
    }

#pragma unroll
    for (int mi = 0; mi < 4; mi++) {
        const int r = m0 + wm * 64 + mi * 16 + g;
#pragma unroll
        for (int ni = 0; ni < 4; ni++) {
            const int c = n0 + wn * 32 + ni * 8 + 2 * tg;
            if constexpr (sizeof(OutT) == 4) {
                *(float2*)&C[(size_t)r * N + c]       = make_float2(acc[mi][ni][0], acc[mi][ni][1]);
                *(float2*)&C[(size_t)(r + 8) * N + c] = make_float2(acc[mi][ni][2], acc[mi][ni][3]);
            } else {
                *(uint32_t*)&C[(size_t)r * N + c]       = pack_h2(acc[mi][ni][0], acc[mi][ni][1]);
                *(uint32_t*)&C[(size_t)(r + 8) * N + c] = pack_h2(acc[mi][ni][2], acc[mi][ni][3]);
            }
        }
    }
}

// Fused launch: CTAs [0,768) -> q GEMM, [768,960) -> kv GEMM,
// [960, 960+4608) -> Wo fp32->fp16 convert (backfills the GEMM tail wave).
#define QK_SPLIT 768
#define QKV_GEMM_CTAS 960
#define QKV_TOTAL (QKV_GEMM_CTAS + CVT_WO_BLKS)
__global__ __launch_bounds__(256, 2)
void gemm_qkv(const __half* __restrict__ ln, const __half* __restrict__ wq,
              __half* __restrict__ q,
              const __half* __restrict__ xn, const __half* __restrict__ wkv,
              __half* __restrict__ kv,
              const float* __restrict__ Wo, __half* __restrict__ woh)
{
    const int bx = blockIdx.x;
    if (bx < QK_SPLIT) {
        gemm_tile<__half>(ln, wq, q, (bx & 31) * 128, (bx >> 5) * 128, HIDDEN, C_DIM);
    } else if (bx < QKV_GEMM_CTAS) {
        const int t = bx - QK_SPLIT;
        gemm_tile<__half>(xn, wkv, kv, (t & 3) * 128, (t >> 2) * 128, KV_DIM, C_DIM);
    } else {
        cvt_block(Wo, woh, bx - QKV_GEMM_CTAS, threadIdx.x);
    }
}

// Plain single GEMM (Wo)
template <typename OutT>
__global__ __launch_bounds__(256, 2)
void gemm_one(const __half* __restrict__ A, const __half* __restrict__ B,
              OutT* __restrict__ C, int N, int K)
{
    gemm_tile<OutT>(A, B, C, blockIdx.x * 128, blockIdx.y * 128, N, K);
}

// ---------------------------------------------------------------------------
// Attention v3 (R13/R16-proven) + ex2-folded softmax scale.
// ---------------------------------------------------------------------------
#define AQ_STR 72
#define ATTN2_SMEM (3 * 128 * AQ_STR * 2)   // 55296 B
#define SCALE_LOG2E 0.1803368801111204f     // 0.125 * log2(e)

__global__ __launch_bounds__(256, 2)
void attn2_kernel(const __half* __restrict__ qh, const __half* __restrict__ kvh,
                  __half* __restrict__ ao)
{
    extern __shared__ __half sm2[];
    const uint32_t sq = smem_u32(sm2);
    const uint32_t sk = sq + 128 * AQ_STR * 2;
    const uint32_t sv = sk + 128 * AQ_STR * 2;

    const int tid  = threadIdx.x;
    const int lane = tid & 31;
    const int w    = tid >> 5;
    const int g    = lane >> 2;
    const int tg   = lane & 3;
    const int cq   = blockIdx.x;
    const int h    = blockIdx.y;
    const int bt   = blockIdx.z;
    const int qr0  = cq * 128;

    const __half* qb = qh  + ((size_t)bt * HW + qr0) * HIDDEN + h * D_HEAD;
    const __half* kb = kvh + (size_t)bt * AA * KV_DIM + h * D_HEAD;
    const __half* vb = kb + HIDDEN;

#pragma unroll
    for (int j = 0; j < 4; j++) {
        const int f = tid + 256 * j;
        const int r = f >> 3, c8 = (f & 7) * 8;
        *(uint4*)(sm2 + r * AQ_STR + c8) = *(const uint4*)(qb + (size_t)r * HIDDEN + c8);
        *(uint4*)(sm2 + 128 * AQ_STR + r * AQ_STR + c8) = *(const uint4*)(kb + (size_t)r * KV_DIM + c8);
        *(uint4*)(sm2 + 2 * 128 * AQ_STR + r * AQ_STR + c8) = *(const uint4*)(vb + (size_t)r * KV_DIM + c8);
    }
    __syncthreads();

    const uint32_t aAddr = sq + (((uint32_t)(w * 16) + (lane & 15)) * AQ_STR + (lane >> 4) * 8) * 2;
    const uint32_t kAddr = sk + ((((lane >> 4) & 1) * 8 + (lane & 7)) * AQ_STR + ((lane >> 3) & 1) * 8) * 2;
    const uint32_t vAddr = sv + ((((lane >> 3) & 1) * 8 + (lane & 7)) * AQ_STR + (lane >> 4) * 8) * 2;

    float sacc[16][4];
#pragma unroll
    for (int j = 0; j < 16; j++)
#pragma unroll
        for (int r = 0; r < 4; r++) sacc[j][r] = 0.f;

#pragma unroll
    for (int ks = 0; ks < 4; ks++) {
        const int k0 = ks * 16;
        uint32_t a[4];
        ldsm_x4(a, aAddr + k0 * 2);
#pragma unroll
        for (int p = 0; p < 8; p++) {
            uint32_t bf[4];
            ldsm_x4(bf, kAddr + (p * 16 * AQ_STR + k0) * 2);
            mma_f16(sacc[2 * p],     a, bf);
            mma_f16(sacc[2 * p + 1], a, bf + 2);
        }
    }

    // softmax over 128 cols in log2 domain: t = s*0.125*log2e; e = ex2(t - max t)
    {
        float mx0 = -FLT_MAX, mx1 = -FLT_MAX;
#pragma unroll
        for (int j = 0; j < 16; j++) {
            sacc[j][0] *= SCALE_LOG2E; sacc[j][1] *= SCALE_LOG2E;
            sacc[j][2] *= SCALE_LOG2E; sacc[j][3] *= SCALE_LOG2E;
            mx0 = fmaxf(mx0, fmaxf(sacc[j][0], sacc[j][1]));
            mx1 = fmaxf(mx1, fmaxf(sacc[j][2], sacc[j][3]));
        }
        mx0 = fmaxf(mx0, __shfl_xor_sync(0xffffffffu, mx0, 1));
        mx0 = fmaxf(mx0, __shfl_xor_sync(0xffffffffu, mx0, 2));
        mx1 = fmaxf(mx1, __shfl_xor_sync(0xffffffffu, mx1, 1));
        mx1 = fmaxf(mx1, __shfl_xor_sync(0xffffffffu, mx1, 2));
        float s0 = 0.f, s1 = 0.f;
#pragma unroll
        for (int j = 0; j < 16; j++) {
            sacc[j][0] = ex2(sacc[j][0] - mx0); s0 += sacc[j][0];
            sacc[j][1] = ex2(sacc[j][1] - mx0); s0 += sacc[j][1];
            sacc[j][2] = ex2(sacc[j][2] - mx1); s1 += sacc[j][2];
            sacc[j][3] = ex2(sacc[j][3] - mx1); s1 += sacc[j][3];
        }
        s0 += __shfl_xor_sync(0xffffffffu, s0, 1);
        s0 += __shfl_xor_sync(0xffffffffu, s0, 2);
        s1 += __shfl_xor_sync(0xffffffffu, s1, 1);
        s1 += __shfl_xor_sync(0xffffffffu, s1, 2);
        const float i0 = 1.0f / s0, i1 = 1.0f / s1;
#pragma unroll
        for (int j = 0; j < 16; j++) {
            sacc[j][0] *= i0; sacc[j][1] *= i0;
            sacc[j][2] *= i1; sacc[j][3] *= i1;
        }
    }

    float oacc[8][4];
#pragma unroll
    for (int j = 0; j < 8; j++)
#pragma unroll
        for (int r = 0; r < 4; r++) oacc[j][r] = 0.f;

#pragma unroll
    for (int t = 0; t < 8; t++) {
        uint32_t pa[4];
        pa[0] = pack_h2(sacc[2 * t][0],     sacc[2 * t][1]);
        pa[1] = pack_h2(sacc[2 * t][2],     sacc[2 * t][3]);
        pa[2] = pack_h2(sacc[2 * t + 1][0], sacc[2 * t + 1][1]);
        pa[3] = pack_h2(sacc[2 * t + 1][2], sacc[2 * t + 1][3]);
#pragma unroll
        for (int p = 0; p < 4; p++) {
            uint32_t bf[4];
            ldsm_x4_t(bf, vAddr + (t * 16 * AQ_STR + p * 16) * 2);
            mma_f16(oacc[2 * p],     pa, bf);
            mma_f16(oacc[2 * p + 1], pa, bf + 2);
        }
    }

    {
        __half* orow0 = ao + ((size_t)bt * HW + qr0 + w * 16 + g) * HIDDEN + h * D_HEAD + 2 * tg;
        __half* orow1 = orow0 + 8 * (size_t)HIDDEN;
#pragma unroll
        for (int j = 0; j < 8; j++) {
            *(uint32_t*)(orow0 + 8 * j) = pack_h2(oacc[j][0], oacc[j][1]);
            *(uint32_t*)(orow1 + 8 * j) = pack_h2(oacc[j][2], oacc[j][3]);
        }
    }
}

// ---------------------------------------------------------------------------
// Launch
// ---------------------------------------------------------------------------
extern "C" void kernel_launch(void* const* d_in, const int* in_sizes, int n_in,
                              void* d_out, int out_size)
{
    const float* x       = (const float*)d_in[0];
    const float* latents = (const float*)d_in[1];
    const float* g1      = (const float*)d_in[2];
    const float* b1      = (const float*)d_in[3];
    const float* g2      = (const float*)d_in[4];
    const float* b2      = (const float*)d_in[5];
    const float* Wq      = (const float*)d_in[6];
    const float* Wkv     = (const float*)d_in[7];
    const float* Wo      = (const float*)d_in[8];
    float* out           = (float*)d_out;

    __half *xnh, *lnh, *qh, *kvh, *aoh, *wqh, *wkvh, *woh;
    cudaGetSymbolAddress((void**)&xnh,  g_xnh);
    cudaGetSymbolAddress((void**)&lnh,  g_lnh);
    cudaGetSymbolAddress((void**)&qh,   g_qh);
    cudaGetSymbolAddress((void**)&kvh,  g_kvh);
    cudaGetSymbolAddress((void**)&aoh,  g_aoh);
    cudaGetSymbolAddress((void**)&wqh,  g_wqh);
    cudaGetSymbolAddress((void**)&wkvh, g_wkvh);
    cudaGetSymbolAddress((void**)&woh,  g_woh);

    cudaFuncSetAttribute(gemm_qkv,        cudaFuncAttributeMaxDynamicSharedMemorySize, G2_SMEM);
    cudaFuncSetAttribute(gemm_one<float>, cudaFuncAttributeMaxDynamicSharedMemorySize, G2_SMEM);
    cudaFuncSetAttribute(attn2_kernel,    cudaFuncAttributeMaxDynamicSharedMemorySize, ATTN2_SMEM);

    prep_kernel<<<PREP_BLKS, 256>>>(Wq, wqh, Wkv, wkvh,
                                    x, latents, g1, b1, g2, b2, xnh, lnh);

    gemm_qkv<<<QKV_TOTAL, 256, G2_SMEM>>>(lnh, wqh, qh, xnh, wkvh, kvh, Wo, woh);

    attn2_kernel<<<dim3(HW / 128, N_HEADS, BT), 256, ATTN2_SMEM>>>(qh, kvh, aoh);

    gemm_one<float><<<dim3(ROWS_L / 128, C_DIM / 128), 256, G2_SMEM>>>(aoh, woh, out, C_DIM, HIDDEN);
}